// round 1
// baseline (speedup 1.0000x reference)
#include <cuda_runtime.h>
#include <stdint.h>

// Problem: out[b][r] = prod_{i=0..7} v(b,i,mf[r][i]),
//   v = 1.0 if idx==-1 else x[b][i][idx]
// Restructure: idx' = idx+1 in {0..4}. Precompute per batch:
//   pair tables (4 pairs x 25), then quad tables (2 quads x 625).
// Each output = qtab[b][off0] * qtab[b][625 + off1]  (2 LDS + 1 mul).
// Rule offsets precomputed once into a __device__ global (packed u16x2).

#define TB 32          // batches per block
#define THREADS 256    // 8 warps
#define NW (THREADS/32)

__device__ uint32_t g_roff[4096];

__global__ void roff_kernel(const int* __restrict__ mf, int n_rules) {
    int r = blockIdx.x * blockDim.x + threadIdx.x;
    if (r >= n_rules) return;
    int po[4];
#pragma unroll
    for (int p = 0; p < 4; ++p) {
        int i0 = mf[r * 8 + 2 * p + 0] + 1;   // 0..4
        int i1 = mf[r * 8 + 2 * p + 1] + 1;   // 0..4
        po[p] = i0 * 5 + i1;                  // 0..24
    }
    uint32_t o0 = (uint32_t)(po[0] * 25 + po[1]);  // 0..624
    uint32_t o1 = (uint32_t)(po[2] * 25 + po[3]);  // 0..624
    g_roff[r] = o0 | (o1 << 16);
}

// Dynamic smem layout (floats):
//   qtab : TB * 1251    (per-batch stride 1251, odd -> conflict-free; quad0 @0..624, quad1 @625..1249)
//   ptab : TB * 101     (pair p @ p*25 .. p*25+24; stride 101 odd)
//   xs   : TB * 33      (x values, col = i*4+m; stride 33 odd)
//   sroff: n_rules u32
//   tiles: NW * 32*33   (per-warp transpose tile, padded)
__global__ __launch_bounds__(THREADS, 1)
void fire_kernel(const float* __restrict__ x, float* __restrict__ out, int n_rules) {
    extern __shared__ float sm[];
    float* qtab = sm;
    float* ptab = qtab + TB * 1251;
    float* xs   = ptab + TB * 101;
    uint32_t* sroff = (uint32_t*)(xs + TB * 33);
    float* tiles = (float*)(sroff + n_rules);

    const int tid  = threadIdx.x;
    const int lane = tid & 31;
    const int wid  = tid >> 5;
    const int b0   = blockIdx.x * TB;

    // ---- stage x tile (TB*32 floats) into xs, padded stride 33 ----
    const float4* x4 = (const float4*)(x + (size_t)b0 * 32);
    for (int j = tid; j < TB * 8; j += THREADS) {
        float4 v = x4[j];
        int base = j * 4;
        int b = base >> 5, c = base & 31;
        float* row = xs + b * 33 + c;
        row[0] = v.x; row[1] = v.y; row[2] = v.z; row[3] = v.w;
    }
    // ---- stage rule offsets ----
    for (int j = tid; j < n_rules; j += THREADS) sroff[j] = g_roff[j];
    __syncthreads();

    // ---- build pair tables: lane = batch (conflict-free) ----
    for (int e = wid; e < 100; e += NW) {
        int p = e / 25, rem = e % 25, a = rem / 5, c = rem % 5;
        float A = (a == 0) ? 1.0f : xs[lane * 33 + p * 8 + (a - 1)];
        float C = (c == 0) ? 1.0f : xs[lane * 33 + p * 8 + 4 + (c - 1)];
        ptab[lane * 101 + e] = A * C;
    }
    __syncthreads();

    // ---- build quad tables: lane = batch (conflict-free) ----
    for (int e = wid; e < 1250; e += NW) {
        int q = e / 625, rem = e % 625, u = rem / 25, v = rem % 25;
        qtab[lane * 1251 + e] =
            ptab[lane * 101 + q * 50 + u] * ptab[lane * 101 + q * 50 + 25 + v];
    }
    __syncthreads();

    // ---- main loop: each warp owns rule-tiles of 32 rules ----
    const float* qb = qtab + lane * 1251;     // this lane's batch table
    float* mytile = tiles + wid * (32 * 33);
    const int nrt = n_rules >> 5;

    for (int rt = wid; rt < nrt; rt += NW) {
        int r0 = rt << 5;
        // gather phase: lane = batch, rule k loops. Conflict-free LDS.
#pragma unroll 8
        for (int k = 0; k < 32; ++k) {
            uint32_t pk = sroff[r0 + k];                 // broadcast
            float v = qb[pk & 0xFFFFu] * qb[625u + (pk >> 16)];
            mytile[k * 33 + lane] = v;                   // row=rule, col=batch
        }
        __syncwarp();
        // write phase: lane = rule -> 128B coalesced STG per batch row
#pragma unroll 8
        for (int bb = 0; bb < 32; ++bb) {
            out[(size_t)(b0 + bb) * n_rules + r0 + lane] = mytile[lane * 33 + bb];
        }
        __syncwarp();
    }
}

extern "C" void kernel_launch(void* const* d_in, const int* in_sizes, int n_in,
                              void* d_out, int out_size) {
    const float* x  = (const float*)d_in[0];
    const int*   mf = (const int*)d_in[1];
    float* out = (float*)d_out;

    const int n_rules = in_sizes[1] / 8;          // 2048
    const int B = in_sizes[0] / 32;               // 8192

    roff_kernel<<<(n_rules + 255) / 256, 256>>>(mf, n_rules);

    size_t smem = (size_t)(TB * 1251 + TB * 101 + TB * 33) * 4
                + (size_t)n_rules * 4
                + (size_t)NW * 32 * 33 * 4;
    cudaFuncSetAttribute(fire_kernel, cudaFuncAttributeMaxDynamicSharedMemorySize, (int)smem);
    fire_kernel<<<B / TB, THREADS, smem>>>(x, out, n_rules);
}

// round 2
// speedup vs baseline: 1.4937x; 1.4937x over previous
#include <cuda_runtime.h>
#include <stdint.h>

// out[b][r] = prod_{i=0..7} v(b,i,mf[r][i]);  v = 1.0 if idx==-1 else x[b][i][idx]
// idx' = idx+1 in {0..4}. Per batch: pair tables (4x25) -> quad tables (2x625).
// Each output = qtab[b][off0] * qtab[b][625+off1].
// Direct scheme: warp unit = (128-rule tile, 16-batch half); lane owns 4 rules,
// loops batches, gathers from the shared per-batch qtab (random-bank LDS),
// writes one STG.128 per batch. 1024 threads/CTA = 32 warps for latency hiding.

#define TB 32
#define THREADS 1024
#define NW (THREADS / 32)

__device__ uint32_t g_roff[4096];

__global__ void roff_kernel(const int* __restrict__ mf, int n_rules) {
    int r = blockIdx.x * blockDim.x + threadIdx.x;
    if (r >= n_rules) return;
    int po[4];
#pragma unroll
    for (int p = 0; p < 4; ++p) {
        int i0 = mf[r * 8 + 2 * p + 0] + 1;   // 0..4
        int i1 = mf[r * 8 + 2 * p + 1] + 1;   // 0..4
        po[p] = i0 * 5 + i1;                  // 0..24
    }
    uint32_t o0 = (uint32_t)(po[0] * 25 + po[1]);  // 0..624
    uint32_t o1 = (uint32_t)(po[2] * 25 + po[3]);  // 0..624
    g_roff[r] = o0 | (o1 << 16);
}

// Dynamic smem (floats):
//   qtab : TB * 1251  (stride 1251: mod 32 = 3 -> lane*stride conflict-free in build)
//   ptab : TB * 101   (stride 101: mod 32 = 5, coprime)
//   xs   : TB * 33
__global__ __launch_bounds__(THREADS, 1)
void fire_kernel(const float* __restrict__ x, float* __restrict__ out, int n_rules) {
    extern __shared__ float sm[];
    float* qtab = sm;
    float* ptab = qtab + TB * 1251;
    float* xs   = ptab + TB * 101;

    const int tid  = threadIdx.x;
    const int lane = tid & 31;
    const int wid  = tid >> 5;
    const int b0   = blockIdx.x * TB;

    // ---- stage x tile (TB*32 floats), padded stride 33 ----
    if (tid < TB * 8) {
        const float4* x4 = (const float4*)(x + (size_t)b0 * 32);
        float4 v = x4[tid];
        int base = tid * 4;
        float* row = xs + (base >> 5) * 33 + (base & 31);
        row[0] = v.x; row[1] = v.y; row[2] = v.z; row[3] = v.w;
    }
    __syncthreads();

    // ---- pair tables: lane = batch (conflict-free) ----
    for (int e = wid; e < 100; e += NW) {
        int p = e / 25, rem = e % 25, a = rem / 5, c = rem % 5;
        float A = (a == 0) ? 1.0f : xs[lane * 33 + p * 8 + (a - 1)];
        float C = (c == 0) ? 1.0f : xs[lane * 33 + p * 8 + 4 + (c - 1)];
        ptab[lane * 101 + e] = A * C;
    }
    __syncthreads();

    // ---- quad tables: lane = batch (conflict-free) ----
    for (int e = wid; e < 1250; e += NW) {
        int q = e / 625, rem = e % 625, u = rem / 25, v = rem % 25;
        qtab[lane * 1251 + e] =
            ptab[lane * 101 + q * 50 + u] * ptab[lane * 101 + q * 50 + 25 + v];
    }
    __syncthreads();

    // ---- main loop: warp unit = (128-rule tile) x (16-batch half) ----
    const int n_units = (n_rules >> 7) * 2;   // 2048 -> 32 units = NW
    for (int u = wid; u < n_units; u += NW) {
        const int rt = u >> 1;
        const int bh = u & 1;
        const int r0 = rt << 7;

        uint4 pk = *(const uint4*)(g_roff + r0 + 4 * lane);
        const int o00 = (int)(pk.x & 0xFFFFu), o01 = 625 + (int)(pk.x >> 16);
        const int o10 = (int)(pk.y & 0xFFFFu), o11 = 625 + (int)(pk.y >> 16);
        const int o20 = (int)(pk.z & 0xFFFFu), o21 = 625 + (int)(pk.z >> 16);
        const int o30 = (int)(pk.w & 0xFFFFu), o31 = 625 + (int)(pk.w >> 16);

        const int bb0 = bh << 4;
        float* outp = out + (size_t)(b0 + bb0) * n_rules + r0 + 4 * lane;
        const float* qb = qtab + (size_t)bb0 * 1251;

#pragma unroll 4
        for (int k = 0; k < 16; ++k) {
            float4 v;
            v.x = qb[o00] * qb[o01];
            v.y = qb[o10] * qb[o11];
            v.z = qb[o20] * qb[o21];
            v.w = qb[o30] * qb[o31];
            *(float4*)outp = v;
            qb   += 1251;
            outp += n_rules;
        }
    }
}

extern "C" void kernel_launch(void* const* d_in, const int* in_sizes, int n_in,
                              void* d_out, int out_size) {
    const float* x  = (const float*)d_in[0];
    const int*   mf = (const int*)d_in[1];
    float* out = (float*)d_out;

    const int n_rules = in_sizes[1] / 8;          // 2048
    const int B = in_sizes[0] / 32;               // 8192

    roff_kernel<<<(n_rules + 255) / 256, 256>>>(mf, n_rules);

    size_t smem = (size_t)(TB * 1251 + TB * 101 + TB * 33) * 4;
    cudaFuncSetAttribute(fire_kernel, cudaFuncAttributeMaxDynamicSharedMemorySize, (int)smem);
    fire_kernel<<<B / TB, THREADS, smem>>>(x, out, n_rules);
}

// round 3
// speedup vs baseline: 2.3338x; 1.5624x over previous
#include <cuda_runtime.h>
#include <stdint.h>

// out[b][r] = prod_{i=0..7} v(b,i,mf[r][i]);  v = 1.0 if idx==-1 else x[b][i][idx]
// Pair-table scheme: per batch, 4 tables of 25 entries:
//   P_p[a*5+c] = A*C, A = (a==0 ? 1 : x[b][2p][a-1]), C likewise for input 2p+1.
// out = P0[o0]*P1[o1]*P2[o2]*P3[o3]  -> 4 LDS per output.
// Within one LDS instruction all lanes read the same (batch,p) table with
// offsets in 0..24 (25 consecutive words) -> distinct banks + broadcast
// => CONFLICT-FREE gathers.
// Persistent grid of 148 CTAs, TB=8 batches/tile, 1024 tiles round-robin.

#define TB 8
#define THREADS 1024
#define NSM 148

__device__ uint32_t g_roff[4096];   // 4 pair-offsets (0..24), 8 bits each

__global__ void roff_kernel(const int* __restrict__ mf, int n_rules) {
    int r = blockIdx.x * blockDim.x + threadIdx.x;
    if (r >= n_rules) return;
    uint32_t pack = 0;
#pragma unroll
    for (int p = 0; p < 4; ++p) {
        int i0 = mf[r * 8 + 2 * p + 0] + 1;   // 0..4
        int i1 = mf[r * 8 + 2 * p + 1] + 1;   // 0..4
        pack |= (uint32_t)(i0 * 5 + i1) << (8 * p);   // 0..24
    }
    g_roff[r] = pack;
}

// smem: ptab[TB][104] floats (per batch: table p at p*25 .. p*25+24)
__global__ __launch_bounds__(THREADS, 1)
void fire_kernel(const float* __restrict__ x, float* __restrict__ out,
                 int n_rules, int n_tiles) {
    __shared__ float ptab[TB * 104];

    const int tid  = threadIdx.x;
    const int lane = tid & 31;
    const int wid  = tid >> 5;

    // decode this warp's rule block once (constant across tiles)
    // warp unit: rule tile rt = wid>>1 (128 rules), batch quarter bq = (wid&1)*4
    const int rt = wid >> 1;
    const int r0 = rt << 7;
    const int bq = (wid & 1) << 2;

    uint4 pk = *(const uint4*)(g_roff + r0 + 4 * lane);
    int c0[4], c1[4], c2[4], c3[4];
#pragma unroll
    for (int p = 0; p < 4; ++p) {
        c0[p] = p * 25 + (int)((pk.x >> (8 * p)) & 255u);
        c1[p] = p * 25 + (int)((pk.y >> (8 * p)) & 255u);
        c2[p] = p * 25 + (int)((pk.z >> (8 * p)) & 255u);
        c3[p] = p * 25 + (int)((pk.w >> (8 * p)) & 255u);
    }

    for (int t = blockIdx.x; t < n_tiles; t += NSM) {
        const int b0 = t * TB;

        // ---- build pair tables: one entry per thread (TB*100 = 800) ----
        if (tid < TB * 100) {
            int b = tid / 100, e = tid % 100;
            int p = e / 25, rem = e % 25, a = rem / 5, c = rem % 5;
            const float* xb = x + (size_t)(b0 + b) * 32 + p * 8;
            float A = (a == 0) ? 1.0f : __ldg(xb + (a - 1));
            float C = (c == 0) ? 1.0f : __ldg(xb + 4 + (c - 1));
            ptab[b * 104 + e] = A * C;
        }
        __syncthreads();

        // ---- main: 4 batches, 128 rules per warp ----
        float* outp = out + (size_t)(b0 + bq) * n_rules + r0 + 4 * lane;
        const float* pb = ptab + (bq) * 104;
#pragma unroll
        for (int k = 0; k < 4; ++k) {
            float4 v;
            v.x = (pb[c0[0]] * pb[c0[1]]) * (pb[c0[2]] * pb[c0[3]]);
            v.y = (pb[c1[0]] * pb[c1[1]]) * (pb[c1[2]] * pb[c1[3]]);
            v.z = (pb[c2[0]] * pb[c2[1]]) * (pb[c2[2]] * pb[c2[3]]);
            v.w = (pb[c3[0]] * pb[c3[1]]) * (pb[c3[2]] * pb[c3[3]]);
            *(float4*)outp = v;
            pb   += 104;
            outp += n_rules;
        }
        __syncthreads();   // protect ptab before next tile's rebuild
    }
}

extern "C" void kernel_launch(void* const* d_in, const int* in_sizes, int n_in,
                              void* d_out, int out_size) {
    const float* x  = (const float*)d_in[0];
    const int*   mf = (const int*)d_in[1];
    float* out = (float*)d_out;

    const int n_rules = in_sizes[1] / 8;          // 2048
    const int B = in_sizes[0] / 32;               // 8192
    const int n_tiles = B / TB;                   // 1024

    roff_kernel<<<(n_rules + 255) / 256, 256>>>(mf, n_rules);
    fire_kernel<<<NSM, THREADS>>>(x, out, n_rules, n_tiles);
}